// round 12
// baseline (speedup 1.0000x reference)
#include <cuda_runtime.h>
#include <cstdint>

// 2D Haar DWT, fp32, input (8, 64, 512, 512) -> 4x (8, 64, 256, 256)
// Output d_out = [ll | lh | hl | hh], each 8*64*256*256 floats.
//
// R12: fully bulk-async streaming. Each 512-thread block:
//   Phase 0: one cp.async.bulk GLOBAL->SMEM of its entire 16 KB input
//            (8 contiguous input rows), mbarrier complete_tx.
//   Phase 1: compute from smem (LDS.128, conflict-free), stage 16 KB out.
//   Phase 2: 4x cp.async.bulk SMEM->GLOBAL (4 KB per subband).
// Reads and writes both presented to DRAM as dense in-order bulks.
// 4 CTAs/SM overlap phases. (R11 = TMA stores only: 154.1us.)

#define PLANES      512          // 8 * 64
#define IN_W        512
#define OUT_W       256
#define OUT_H       256
#define PLANE_IN_F    (IN_W * 512)         // 262144 floats per input plane
#define ROW_OUT_F2    (OUT_W / 2)          // 128 float2 per output row
#define SUBBAND_ELEMS (PLANES * OUT_W * OUT_H)  // 33554432 floats per subband

#define BLOCK_THR   512
#define IN_BYTES    16384                  // 8 input rows * 2 KB
#define SUB_BYTES   (BLOCK_THR * 8)        // 4096 bytes per subband per block

__global__ __launch_bounds__(BLOCK_THR)
void dwt2d_haar_kernel(const float* __restrict__ in,
                       float* __restrict__ out)
{
    __shared__ alignas(128) float4 sin4[IN_BYTES / 16];      // 16 KB input
    __shared__ alignas(128) float2 sout[4][BLOCK_THR];       // 16 KB staged
    __shared__ alignas(8)  uint64_t mbar;

    unsigned tid = threadIdx.x;
    unsigned bid = blockIdx.x;

    uint32_t mbar_a;
    asm("{ .reg .u64 t; cvta.to.shared.u64 t, %1; cvt.u32.u64 %0, t; }"
        : "=r"(mbar_a) : "l"(&mbar));

    // ---- Phase 0: bulk-load this block's contiguous 16 KB input ----
    // Block covers output items [bid*512, bid*512+512) = plane p,
    // output rows oy0..oy0+3 -> input rows 2*oy0..2*oy0+7 (contiguous).
    unsigned p   = bid >> 6;                   // 64 blocks per plane
    unsigned oy0 = (bid & 63u) * 4u;           // first output row of block
    const float* gin = in + (size_t)p * PLANE_IN_F + (size_t)(2u * oy0) * IN_W;

    if (tid == 0) {
        asm volatile("mbarrier.init.shared.b64 [%0], 1;" :: "r"(mbar_a) : "memory");
    }
    __syncthreads();
    if (tid == 0) {
        asm volatile("mbarrier.arrive.expect_tx.shared.b64 _, [%0], %1;"
                     :: "r"(mbar_a), "r"((uint32_t)IN_BYTES) : "memory");
        uint32_t sdst;
        asm("{ .reg .u64 t; cvta.to.shared.u64 t, %1; cvt.u32.u64 %0, t; }"
            : "=r"(sdst) : "l"(&sin4[0]));
        asm volatile(
            "cp.async.bulk.shared::cta.global.mbarrier::complete_tx::bytes "
            "[%0], [%1], %2, [%3];"
            :: "r"(sdst), "l"(gin), "r"((uint32_t)IN_BYTES), "r"(mbar_a)
            : "memory");
    }
    // All threads wait for the bulk load (phase parity 0, single use).
    asm volatile(
        "{\n\t"
        ".reg .pred P1;\n\t"
        "WAIT_%=:\n\t"
        "mbarrier.try_wait.parity.acquire.cta.shared::cta.b64 P1, [%0], 0, 0x989680;\n\t"
        "@P1 bra.uni DONE_%=;\n\t"
        "bra.uni WAIT_%=;\n\t"
        "DONE_%=:\n\t"
        "}"
        :: "r"(mbar_a) : "memory");

    // ---- Phase 1: compute from smem, stage results ----
    unsigned lox2 = tid & (ROW_OUT_F2 - 1);    // 0..127 (col pair)
    unsigned loy  = tid >> 7;                  // 0..3   (local out row)

    // input rows 2*loy, 2*loy+1 within the 8-row tile; 128 float4 per row
    float4 r0 = sin4[(2u * loy)     * 128u + lox2];
    float4 r1 = sin4[(2u * loy + 1) * 128u + lox2];

    float a0 = r0.x, b0 = r0.y, c0 = r1.x, d0 = r1.y;
    float a1 = r0.z, b1 = r0.w, c1 = r1.z, d1 = r1.w;

    const float half = 0.5f;
    float2 vll, vlh, vhl, vhh;
    vll.x = (a0 + b0 + c0 + d0) * half;
    vll.y = (a1 + b1 + c1 + d1) * half;
    vlh.x = (c0 + d0 - a0 - b0) * half;
    vlh.y = (c1 + d1 - a1 - b1) * half;
    vhl.x = (b0 + d0 - a0 - c0) * half;
    vhl.y = (b1 + d1 - a1 - c1) * half;
    vhh.x = (a0 + d0 - b0 - c0) * half;
    vhh.y = (a1 + d1 - b1 - c1) * half;

    sout[0][tid] = vll;
    sout[1][tid] = vlh;
    sout[2][tid] = vhl;
    sout[3][tid] = vhh;

    __syncthreads();

    // ---- Phase 2: bulk-store 4 KB per subband ----
    if (tid == 0) {
        asm volatile("fence.proxy.async.shared::cta;" ::: "memory");
        size_t base_f = (size_t)bid * (2u * BLOCK_THR);   // float offset
        #pragma unroll
        for (int sub = 0; sub < 4; sub++) {
            float* gptr = out + (size_t)sub * SUBBAND_ELEMS + base_f;
            uint32_t saddr;
            asm("{ .reg .u64 t; cvta.to.shared.u64 t, %1; cvt.u32.u64 %0, t; }"
                : "=r"(saddr) : "l"(&sout[sub][0]));
            asm volatile(
                "cp.async.bulk.global.shared::cta.bulk_group [%0], [%1], %2;"
                :: "l"(gptr), "r"(saddr), "r"((uint32_t)SUB_BYTES)
                : "memory");
        }
        asm volatile("cp.async.bulk.commit_group;" ::: "memory");
        asm volatile("cp.async.bulk.wait_group.read 0;" ::: "memory");
        asm volatile("mbarrier.inval.shared.b64 [%0];" :: "r"(mbar_a) : "memory");
    }
    // Hold CTA (and smem) until bulk read-out completes.
    __syncthreads();
}

extern "C" void kernel_launch(void* const* d_in, const int* in_sizes, int n_in,
                              void* d_out, int out_size)
{
    const float* in = (const float*)d_in[0];
    float* out = (float*)d_out;

    const unsigned total_threads = PLANES * OUT_H * ROW_OUT_F2;  // 16,777,216
    const unsigned grid = total_threads / BLOCK_THR;             // 32,768

    dwt2d_haar_kernel<<<grid, BLOCK_THR>>>(in, out);
}

// round 13
// speedup vs baseline: 1.0369x; 1.0369x over previous
#include <cuda_runtime.h>
#include <cstdint>

// 2D Haar DWT, fp32, input (8, 64, 512, 512) -> 4x (8, 64, 256, 256)
// Output d_out = [ll | lh | hl | hh], each 8*64*256*256 floats.
//
// R13: R11 (best: 154.1us; LDG.128 reads + TMA bulk stores) with the four
// 4 KB subband stores issued by four different warps (elected lane each,
// own bulk group), and no trailing block barrier: non-issuing warps exit,
// CTA retires when the four issuing threads finish wait_group.read.

#define PLANES      512          // 8 * 64
#define IN_W        512
#define OUT_W       256
#define OUT_H       256
#define PLANE_IN_F4   (IN_W * 512 / 4)     // 65536 float4 per input plane
#define ROW_IN_F4     (IN_W / 4)           // 128 float4 per input row
#define ROW_OUT_F2    (OUT_W / 2)          // 128 float2 per output row
#define SUBBAND_ELEMS (PLANES * OUT_W * OUT_H)  // 33554432 floats per subband

#define BLOCK_THR   512
#define SUB_BYTES   (BLOCK_THR * 8)        // 4096 bytes per subband per block

__global__ __launch_bounds__(BLOCK_THR)
void dwt2d_haar_kernel(const float4* __restrict__ x4,
                       float* __restrict__ out)
{
    __shared__ alignas(128) float2 s[4][BLOCK_THR];   // 16 KB staged output

    unsigned tid  = threadIdx.x;
    unsigned item = blockIdx.x * BLOCK_THR + tid;
    // item == output float2 index within each subband (exact identity).

    // ---- Phase 1: 2x LDG.128 (L1-bypass), compute, stage to smem ----
    unsigned ox2 = item & (ROW_OUT_F2 - 1);         // 0..127
    unsigned t1  = item >> 7;
    unsigned oy  = t1 & (OUT_H - 1);                // 0..255
    unsigned p   = t1 >> 8;                         // 0..511

    unsigned in_base = p * PLANE_IN_F4 + (2u * oy) * ROW_IN_F4 + ox2;
    float4 r0 = __ldcg(&x4[in_base]);               // row 2y,   cols 4x..4x+3
    float4 r1 = __ldcg(&x4[in_base + ROW_IN_F4]);   // row 2y+1

    float a0 = r0.x, b0 = r0.y, c0 = r1.x, d0 = r1.y;
    float a1 = r0.z, b1 = r0.w, c1 = r1.z, d1 = r1.w;

    const float half = 0.5f;
    float2 vll, vlh, vhl, vhh;
    vll.x = (a0 + b0 + c0 + d0) * half;
    vll.y = (a1 + b1 + c1 + d1) * half;
    vlh.x = (c0 + d0 - a0 - b0) * half;
    vlh.y = (c1 + d1 - a1 - b1) * half;
    vhl.x = (b0 + d0 - a0 - c0) * half;
    vhl.y = (b1 + d1 - a1 - c1) * half;
    vhh.x = (a0 + d0 - b0 - c0) * half;
    vhh.y = (a1 + d1 - b1 - c1) * half;

    s[0][tid] = vll;
    s[1][tid] = vlh;
    s[2][tid] = vhl;
    s[3][tid] = vhh;

    __syncthreads();

    // ---- Phase 2: 4x TMA bulk store (4 KB each), one per warp 0..3. ----
    unsigned wid = tid >> 5;
    if (wid < 4) {
        // elect one lane per warp
        uint32_t epred;
        asm volatile(
            "{\n\t"
            ".reg .pred p;\n\t"
            "elect.sync _|p, 0xFFFFFFFF;\n\t"
            "selp.b32 %0, 1, 0, p;\n\t"
            "}" : "=r"(epred));
        if (epred) {
            asm volatile("fence.proxy.async.shared::cta;" ::: "memory");
            unsigned sub = wid;
            // block owns float2 range [blockIdx.x*512, +512) in each subband
            size_t base_f = (size_t)blockIdx.x * (2u * BLOCK_THR);
            float* gptr = out + (size_t)sub * SUBBAND_ELEMS + base_f;
            uint32_t saddr;
            asm("{ .reg .u64 t; cvta.to.shared.u64 t, %1; cvt.u32.u64 %0, t; }"
                : "=r"(saddr) : "l"(&s[sub][0]));
            asm volatile(
                "cp.async.bulk.global.shared::cta.bulk_group [%0], [%1], %2;"
                :: "l"(gptr), "r"(saddr), "r"((uint32_t)SUB_BYTES)
                : "memory");
            asm volatile("cp.async.bulk.commit_group;" ::: "memory");
            // Wait until smem read-out done; global writes drain async.
            asm volatile("cp.async.bulk.wait_group.read 0;" ::: "memory");
        }
    }
    // Non-issuing threads exit; CTA (and smem) persists until the four
    // issuing threads complete their wait_group.
}

extern "C" void kernel_launch(void* const* d_in, const int* in_sizes, int n_in,
                              void* d_out, int out_size)
{
    const float4* x4 = (const float4*)d_in[0];
    float* out = (float*)d_out;

    const unsigned total_threads = PLANES * OUT_H * ROW_OUT_F2;  // 16,777,216
    const unsigned grid = total_threads / BLOCK_THR;             // 32,768

    dwt2d_haar_kernel<<<grid, BLOCK_THR>>>(x4, out);
}